// round 1
// baseline (speedup 1.0000x reference)
#include <cuda_runtime.h>
#include <cuda_bf16.h>
#include <float.h>

// ============================================================================
// KolmogorovArnoldNetwork: per-channel 3-layer MLP on a SCALAR input.
// Exact piecewise-linear reformulation:
//   For each channel c, out_o(x) is piecewise linear in x.
//   Layer-1 relu thresholds t_h = -b1/w1 give 257 intervals (sorted).
//   Within interval i: g_k(x) = A_i[k]*x + B_i[k] + b2[k]  (A,B via prefix scan)
//   Layer-2 relu adds <=1 zero-crossing per k per interval.
//   out_o = sum_k relu(g_k) W3[k,o] + b3 ->  P*x + Q per segment.
// Kernels:
//   K1: per-channel threshold sort + prefix scan -> A_i[k], B_i[k]   (16 CTAs)
//   K2: per (channel, interval): crossings, sort, segment coeffs     (4112 CTAs)
//   K3: per (pixel, channel): 2-level binary search + 3 FMAs         (2048 CTAs)
// ============================================================================

#define CHN   16
#define HID   256
#define NIV   257
#define XMAXV 64.0f     // |x| data max ~4.8; clamp table domain to +/-64

// Scratch (device globals; no allocation)
__device__ float g_t  [CHN][HID];             // sorted thresholds
__device__ float g_A  [CHN][NIV][HID];        // slope table per interval
__device__ float g_Bv [CHN][NIV][HID];        // intercept table per interval
__device__ int   g_cnt[CHN][NIV];             // crossings per interval
__device__ float g_xc [CHN][NIV][HID];        // sorted crossing x's
__device__ __align__(16) float g_PQ[CHN][NIV][NIV][8];  // P0,P1,P2,Q0,Q1,Q2 per segment

// ---------------------------------------------------------------------------
// K1: sort thresholds, prefix-scan A/B tables (block = channel, thread = k)
// ---------------------------------------------------------------------------
__global__ void __launch_bounds__(256) k_scan(const float* __restrict__ W1,
                                              const float* __restrict__ B1,
                                              const float* __restrict__ W2)
{
    int c   = blockIdx.x;
    int tid = threadIdx.x;

    __shared__ float    key[HID];
    __shared__ unsigned idx[HID];
    __shared__ float    ca0[HID], cb0[HID];   // base (x -> -inf) coefficients, by h
    __shared__ float    ca1[HID], cb1[HID];   // toggle coefficients, by sorted pos j

    float w1 = W1[c * HID + tid];
    float b1 = B1[c * HID + tid];

    // threshold; w1==0 never toggles (sentinel sorts last)
    float t = (w1 != 0.0f) ? (-b1 / w1) : 3.0e38f;
    key[tid] = t;
    idx[tid] = (unsigned)tid;

    // active as x -> -inf:  w1<0, or w1==0 && b1>0 (always active)
    bool base = (w1 < 0.0f) || (w1 == 0.0f && b1 > 0.0f);
    ca0[tid] = base ? w1 : 0.0f;
    cb0[tid] = base ? b1 : 0.0f;

    __shared__ float sw1[HID], sb1[HID];
    sw1[tid] = w1; sb1[tid] = b1;
    __syncthreads();

    // bitonic sort (key asc, carry h index)
    for (unsigned size = 2; size <= HID; size <<= 1) {
        for (unsigned stride = size >> 1; stride; stride >>= 1) {
            __syncthreads();
            unsigned partner = (unsigned)tid ^ stride;
            if (partner > (unsigned)tid) {
                bool up = ((tid & size) == 0);
                float k1 = key[tid], k2 = key[partner];
                if ((k1 > k2) == up) {
                    key[tid] = k2; key[partner] = k1;
                    unsigned v = idx[tid]; idx[tid] = idx[partner]; idx[partner] = v;
                }
            }
        }
    }
    __syncthreads();

    g_t[c][tid] = key[tid];

    // toggle coefficients by sorted position: +w1 (turn on) for w1>0, -w1 for w1<0
    {
        unsigned h = idx[tid];
        float w = sw1[h], b = sb1[h];
        float s = (w > 0.0f) ? 1.0f : ((w < 0.0f) ? -1.0f : 0.0f);
        ca1[tid] = s * w;
        cb1[tid] = s * b;
    }
    __syncthreads();

    // prefix scan over k = tid
    int k = tid;
    float A = 0.0f, B = 0.0f;
    #pragma unroll 4
    for (int h = 0; h < HID; h++) {
        float w2 = W2[(c * HID + h) * HID + k];
        A = fmaf(ca0[h], w2, A);
        B = fmaf(cb0[h], w2, B);
    }
    g_A[c][0][k] = A; g_Bv[c][0][k] = B;

    #pragma unroll 4
    for (int j = 0; j < HID; j++) {
        unsigned h = idx[j];
        float w2 = W2[(c * HID + h) * HID + k];
        A = fmaf(ca1[j], w2, A);
        B = fmaf(cb1[j], w2, B);
        g_A[c][j + 1][k] = A; g_Bv[c][j + 1][k] = B;
    }
}

// ---------------------------------------------------------------------------
// K2: per (interval, channel): find layer-2 crossings, sort, emit segments
// ---------------------------------------------------------------------------
__global__ void __launch_bounds__(256) k_seg(const float* __restrict__ B2,
                                             const float* __restrict__ W3,
                                             const float* __restrict__ B3)
{
    int i   = blockIdx.x;   // 0..256
    int c   = blockIdx.y;
    int tid = threadIdx.x;  // = k

    __shared__ float    sA[HID], sB[HID];
    __shared__ float    sW3[HID][3];
    __shared__ float    red[6][HID];
    __shared__ float    skey[HID];
    __shared__ unsigned spay[HID];
    __shared__ int      wcnt[8];
    __shared__ int      s_m;

    float A  = g_A [c][i][tid];
    float Bb = g_Bv[c][i][tid] + B2[c * HID + tid];
    sA[tid] = A; sB[tid] = Bb;

    float w30 = W3[(c * HID + tid) * 3 + 0];
    float w31 = W3[(c * HID + tid) * 3 + 1];
    float w32 = W3[(c * HID + tid) * 3 + 2];
    sW3[tid][0] = w30; sW3[tid][1] = w31; sW3[tid][2] = w32;

    float lo = (i == 0)   ? -XMAXV : g_t[c][i - 1];
    float hi = (i == 256) ?  XMAXV : g_t[c][i];
    lo = fminf(fmaxf(lo, -XMAXV), XMAXV);
    hi = fminf(fmaxf(hi, -XMAXV), XMAXV);
    if (hi < lo) hi = lo;

    float gl = fmaf(A, lo, Bb);
    float gh = fmaf(A, hi, Bb);
    bool  aL = gl > 0.0f;

    red[0][tid] = aL ? A  * w30 : 0.0f;
    red[1][tid] = aL ? A  * w31 : 0.0f;
    red[2][tid] = aL ? A  * w32 : 0.0f;
    red[3][tid] = aL ? Bb * w30 : 0.0f;
    red[4][tid] = aL ? Bb * w31 : 0.0f;
    red[5][tid] = aL ? Bb * w32 : 0.0f;
    __syncthreads();
    for (int s = 128; s > 0; s >>= 1) {
        if (tid < s) {
            #pragma unroll
            for (int q = 0; q < 6; q++) red[q][tid] += red[q][tid + s];
        }
        __syncthreads();
    }

    // layer-2 zero-crossing inside (lo,hi)?
    bool  has = ((gl > 0.0f) != (gh > 0.0f));
    float xc  = 0.0f;
    if (has) xc = lo + (hi - lo) * (gl / (gl - gh));
    unsigned pay = (unsigned)tid | ((gh > 0.0f) ? 256u : 0u);  // bit8: turns ON

    // deterministic compaction (warp ballot + block prefix)
    unsigned mask = __ballot_sync(0xFFFFFFFFu, has);
    int warp = tid >> 5, lane = tid & 31;
    if (lane == 0) wcnt[warp] = __popc(mask);
    __syncthreads();
    if (tid == 0) {
        int acc = 0;
        for (int w = 0; w < 8; w++) { int t2 = wcnt[w]; wcnt[w] = acc; acc += t2; }
        s_m = acc;
    }
    __syncthreads();
    int m = s_m;
    if (has) {
        int d = wcnt[warp] + __popc(mask & ((1u << lane) - 1u));
        skey[d] = xc; spay[d] = pay;
    }
    if (tid >= m) { skey[tid] = 3.4e38f; spay[tid] = 0u; }
    __syncthreads();

    if (m > 1) {  // uniform branch
        for (unsigned size = 2; size <= HID; size <<= 1) {
            for (unsigned stride = size >> 1; stride; stride >>= 1) {
                __syncthreads();
                unsigned partner = (unsigned)tid ^ stride;
                if (partner > (unsigned)tid) {
                    bool up = ((tid & size) == 0);
                    float k1 = skey[tid], k2 = skey[partner];
                    if ((k1 > k2) == up) {
                        skey[tid] = k2; skey[partner] = k1;
                        unsigned v = spay[tid]; spay[tid] = spay[partner]; spay[partner] = v;
                    }
                }
            }
        }
        __syncthreads();
    }

    if (tid == 0) {
        g_cnt[c][i] = m;
        float P0 = red[0][0], P1 = red[1][0], P2 = red[2][0];
        float Q0 = red[3][0] + B3[c * 3 + 0];
        float Q1 = red[4][0] + B3[c * 3 + 1];
        float Q2 = red[5][0] + B3[c * 3 + 2];
        float* pq = &g_PQ[c][i][0][0];
        pq[0] = P0; pq[1] = P1; pq[2] = P2; pq[3] = Q0; pq[4] = Q1; pq[5] = Q2;
        for (int j = 0; j < m; j++) {
            unsigned p = spay[j];
            int   kk = (int)(p & 255u);
            float d  = (p & 256u) ? 1.0f : -1.0f;
            float a  = sA[kk], bb = sB[kk];
            float u0 = sW3[kk][0], u1 = sW3[kk][1], u2 = sW3[kk][2];
            P0 = fmaf(d * a,  u0, P0); P1 = fmaf(d * a,  u1, P1); P2 = fmaf(d * a,  u2, P2);
            Q0 = fmaf(d * bb, u0, Q0); Q1 = fmaf(d * bb, u1, Q1); Q2 = fmaf(d * bb, u2, Q2);
            g_xc[c][i][j] = skey[j];
            float* pq2 = &g_PQ[c][i][j + 1][0];
            pq2[0] = P0; pq2[1] = P1; pq2[2] = P2; pq2[3] = Q0; pq2[4] = Q1; pq2[5] = Q2;
        }
    }
}

// ---------------------------------------------------------------------------
// K3: evaluation. p = n*16 + c; out[p*3 + o]
// ---------------------------------------------------------------------------
__global__ void __launch_bounds__(256) k_eval(const float* __restrict__ X,
                                              float* __restrict__ out)
{
    __shared__ float st[CHN][HID];
    int tid = threadIdx.x;
    for (int q = tid; q < CHN * HID; q += 256)
        (&st[0][0])[q] = (&g_t[0][0])[q];
    __syncthreads();

    int p = blockIdx.x * 256 + tid;
    float x = X[p];
    int c = p & 15;

    // level 1: interval (exactly 8 steps)
    int lo = 0, hi = HID;
    #pragma unroll
    for (int s = 0; s < 8; s++) {
        int mid = (lo + hi) >> 1;
        if (st[c][mid] <= x) lo = mid + 1; else hi = mid;
    }
    int i = lo;

    // level 2: segment within interval
    int m = g_cnt[c][i];
    int j = 0, jh = m;
    while (j < jh) {
        int mid = (j + jh) >> 1;
        if (g_xc[c][i][mid] <= x) j = mid + 1; else jh = mid;
    }

    const float4* pq = (const float4*)&g_PQ[c][i][j][0];
    float4 a = pq[0];
    float4 b = pq[1];
    float* o = out + p * 3;
    o[0] = fmaf(a.x, x, a.w);
    o[1] = fmaf(a.y, x, b.x);
    o[2] = fmaf(a.z, x, b.y);
}

// ---------------------------------------------------------------------------
extern "C" void kernel_launch(void* const* d_in, const int* in_sizes, int n_in,
                              void* d_out, int out_size)
{
    const float* x  = (const float*)d_in[0];
    const float* W1 = (const float*)d_in[1];
    const float* b1 = (const float*)d_in[2];
    const float* W2 = (const float*)d_in[3];
    const float* b2 = (const float*)d_in[4];
    const float* W3 = (const float*)d_in[5];
    const float* b3 = (const float*)d_in[6];
    float* out = (float*)d_out;

    k_scan<<<CHN, 256>>>(W1, b1, W2);
    k_seg <<<dim3(NIV, CHN), 256>>>(b2, W3, b3);
    k_eval<<<(32768 * CHN) / 256, 256>>>(x, out);
}

// round 2
// speedup vs baseline: 1.5475x; 1.5475x over previous
#include <cuda_runtime.h>
#include <cuda_bf16.h>
#include <float.h>

// ============================================================================
// KolmogorovArnoldNetwork: exact piecewise-linear reformulation (see R1).
// R2: two-level decoupled prefix scan (16 -> 256 CTAs), slim k_seg
//     (shuffle reduction + size-adaptive bitonic).
// ============================================================================

#define CHN   16
#define HID   256
#define NIV   257
#define XMAXV 64.0f
#define NG    16          // groups per channel
#define GS    16          // toggles per group (NG*GS == HID)

// Scratch (device globals; no allocation)
__device__ float g_t   [CHN][HID];            // sorted thresholds
__device__ int   g_idx [CHN][HID];            // sorted h index
__device__ float g_ca0 [CHN][HID];            // base coeff (by sorted pos)
__device__ float g_cb0 [CHN][HID];
__device__ float g_ca1 [CHN][HID];            // toggle coeff (by sorted pos)
__device__ float g_cb1 [CHN][HID];
__device__ float g_SbA [CHN][NG][HID];        // per-group base partial (A)
__device__ float g_SbB [CHN][NG][HID];
__device__ float g_StA [CHN][NG][HID];        // per-group toggle total (A)
__device__ float g_StB [CHN][NG][HID];
__device__ float g_A   [CHN][NIV][HID];       // slope table per interval
__device__ float g_Bv  [CHN][NIV][HID];       // intercept table per interval
__device__ int   g_cnt [CHN][NIV];            // crossings per interval
__device__ float g_xc  [CHN][NIV][HID];       // sorted crossing x's
__device__ __align__(16) float g_PQ[CHN][NIV][NIV][8];  // P0..P2,Q0..Q2

// ---------------------------------------------------------------------------
// K1-sort: per channel, sort thresholds, emit base/toggle coeffs by sorted pos
// ---------------------------------------------------------------------------
__global__ void __launch_bounds__(256) k_sort(const float* __restrict__ W1,
                                              const float* __restrict__ B1)
{
    int c   = blockIdx.x;
    int tid = threadIdx.x;

    __shared__ float    key[HID];
    __shared__ unsigned idx[HID];
    __shared__ float    sw1[HID], sb1[HID];

    float w1 = W1[c * HID + tid];
    float b1 = B1[c * HID + tid];
    sw1[tid] = w1; sb1[tid] = b1;

    float t = (w1 != 0.0f) ? (-b1 / w1) : 3.0e38f;   // sentinel sorts last
    key[tid] = t;
    idx[tid] = (unsigned)tid;

    // bitonic sort asc
    for (unsigned size = 2; size <= HID; size <<= 1) {
        for (unsigned stride = size >> 1; stride; stride >>= 1) {
            __syncthreads();
            unsigned partner = (unsigned)tid ^ stride;
            if (partner > (unsigned)tid) {
                bool up = ((tid & size) == 0);
                float k1 = key[tid], k2 = key[partner];
                if ((k1 > k2) == up) {
                    key[tid] = k2; key[partner] = k1;
                    unsigned v = idx[tid]; idx[tid] = idx[partner]; idx[partner] = v;
                }
            }
        }
    }
    __syncthreads();

    g_t[c][tid] = key[tid];
    unsigned h = idx[tid];
    g_idx[c][tid] = (int)h;

    float w = sw1[h], b = sb1[h];
    // active as x -> -inf:  w<0, or w==0 && b>0
    bool base = (w < 0.0f) || (w == 0.0f && b > 0.0f);
    g_ca0[c][tid] = base ? w : 0.0f;
    g_cb0[c][tid] = base ? b : 0.0f;
    float s = (w > 0.0f) ? 1.0f : ((w < 0.0f) ? -1.0f : 0.0f);
    g_ca1[c][tid] = s * w;
    g_cb1[c][tid] = s * b;
}

// ---------------------------------------------------------------------------
// K1a: per (group, channel): base partial + toggle group total
// ---------------------------------------------------------------------------
__global__ void __launch_bounds__(256) k_gsum(const float* __restrict__ W2)
{
    int g = blockIdx.x, c = blockIdx.y, k = threadIdx.x;

    float sbA = 0.f, sbB = 0.f, stA = 0.f, stB = 0.f;
    #pragma unroll
    for (int jj = 0; jj < GS; jj++) {
        int j = g * GS + jj;
        int h = g_idx[c][j];
        float w2 = W2[(c * HID + h) * HID + k];
        sbA = fmaf(g_ca0[c][j], w2, sbA);
        sbB = fmaf(g_cb0[c][j], w2, sbB);
        stA = fmaf(g_ca1[c][j], w2, stA);
        stB = fmaf(g_cb1[c][j], w2, stB);
    }
    g_SbA[c][g][k] = sbA; g_SbB[c][g][k] = sbB;
    g_StA[c][g][k] = stA; g_StB[c][g][k] = stB;
}

// ---------------------------------------------------------------------------
// K1b: per (group, channel): offset from partials, 16-step local prefix
// ---------------------------------------------------------------------------
__global__ void __launch_bounds__(256) k_prefix(const float* __restrict__ W2)
{
    int g = blockIdx.x, c = blockIdx.y, k = threadIdx.x;

    float A = 0.f, B = 0.f;
    #pragma unroll
    for (int g2 = 0; g2 < NG; g2++) {     // full base
        A += g_SbA[c][g2][k];
        B += g_SbB[c][g2][k];
    }
    for (int g2 = 0; g2 < g; g2++) {      // toggles of earlier groups
        A += g_StA[c][g2][k];
        B += g_StB[c][g2][k];
    }
    if (g == 0) { g_A[c][0][k] = A; g_Bv[c][0][k] = B; }

    #pragma unroll
    for (int jj = 0; jj < GS; jj++) {
        int j = g * GS + jj;
        int h = g_idx[c][j];
        float w2 = W2[(c * HID + h) * HID + k];
        A = fmaf(g_ca1[c][j], w2, A);
        B = fmaf(g_cb1[c][j], w2, B);
        g_A[c][j + 1][k] = A; g_Bv[c][j + 1][k] = B;
    }
}

// ---------------------------------------------------------------------------
// K2: per (interval, channel): crossings, adaptive sort, segment coeffs
// ---------------------------------------------------------------------------
__global__ void __launch_bounds__(256) k_seg(const float* __restrict__ B2,
                                             const float* __restrict__ W3,
                                             const float* __restrict__ B3)
{
    int i   = blockIdx.x;   // 0..256
    int c   = blockIdx.y;
    int tid = threadIdx.x;  // = k

    __shared__ float    sA[HID], sB[HID];
    __shared__ float    sW3[HID][3];
    __shared__ float    swred[8][6];
    __shared__ float    skey[HID];
    __shared__ unsigned spay[HID];
    __shared__ int      wcnt[8];
    __shared__ int      s_m;

    float A  = g_A [c][i][tid];
    float Bb = g_Bv[c][i][tid] + B2[c * HID + tid];
    sA[tid] = A; sB[tid] = Bb;

    float w30 = W3[(c * HID + tid) * 3 + 0];
    float w31 = W3[(c * HID + tid) * 3 + 1];
    float w32 = W3[(c * HID + tid) * 3 + 2];
    sW3[tid][0] = w30; sW3[tid][1] = w31; sW3[tid][2] = w32;

    float lo = (i == 0)   ? -XMAXV : g_t[c][i - 1];
    float hi = (i == 256) ?  XMAXV : g_t[c][i];
    lo = fminf(fmaxf(lo, -XMAXV), XMAXV);
    hi = fminf(fmaxf(hi, -XMAXV), XMAXV);
    if (hi < lo) hi = lo;

    float gl = fmaf(A, lo, Bb);
    float gh = fmaf(A, hi, Bb);
    bool  aL = gl > 0.0f;

    // 6-way reduction: warp shuffle, then thread 0 sums 8 warp rows
    float v[6];
    v[0] = aL ? A  * w30 : 0.0f;
    v[1] = aL ? A  * w31 : 0.0f;
    v[2] = aL ? A  * w32 : 0.0f;
    v[3] = aL ? Bb * w30 : 0.0f;
    v[4] = aL ? Bb * w31 : 0.0f;
    v[5] = aL ? Bb * w32 : 0.0f;
    #pragma unroll
    for (int off = 16; off; off >>= 1)
        #pragma unroll
        for (int q = 0; q < 6; q++)
            v[q] += __shfl_down_sync(0xFFFFFFFFu, v[q], off);
    int warp = tid >> 5, lane = tid & 31;
    if (lane == 0)
        #pragma unroll
        for (int q = 0; q < 6; q++) swred[warp][q] = v[q];

    // layer-2 zero-crossing inside (lo,hi)?
    bool  has = ((gl > 0.0f) != (gh > 0.0f));
    float xc  = 0.0f;
    if (has) xc = lo + (hi - lo) * (gl / (gl - gh));
    unsigned pay = (unsigned)tid | ((gh > 0.0f) ? 256u : 0u);  // bit8: turns ON

    unsigned mask = __ballot_sync(0xFFFFFFFFu, has);
    if (lane == 0) wcnt[warp] = __popc(mask);
    __syncthreads();
    if (tid == 0) {
        int acc = 0;
        #pragma unroll
        for (int w = 0; w < 8; w++) { int t2 = wcnt[w]; wcnt[w] = acc; acc += t2; }
        s_m = acc;
    }
    __syncthreads();
    int m = s_m;
    if (has) {
        int d = wcnt[warp] + __popc(mask & ((1u << lane) - 1u));
        skey[d] = xc; spay[d] = pay;
    }
    if (tid >= m) { skey[tid] = 3.4e38f; spay[tid] = 0u; }
    __syncthreads();

    if (m > 1) {
        // bitonic over next-pow2(m) only (uniform S)
        unsigned S = 2;
        while ((int)S < m) S <<= 1;
        for (unsigned size = 2; size <= S; size <<= 1) {
            for (unsigned stride = size >> 1; stride; stride >>= 1) {
                __syncthreads();
                unsigned partner = (unsigned)tid ^ stride;
                if ((unsigned)tid < S && partner > (unsigned)tid) {
                    bool up = ((tid & size) == 0);
                    float k1 = skey[tid], k2 = skey[partner];
                    if ((k1 > k2) == up) {
                        skey[tid] = k2; skey[partner] = k1;
                        unsigned vv = spay[tid]; spay[tid] = spay[partner]; spay[partner] = vv;
                    }
                }
            }
        }
        __syncthreads();
    }

    if (tid == 0) {
        g_cnt[c][i] = m;
        float P0 = swred[0][0], P1 = swred[0][1], P2 = swred[0][2];
        float Q0 = swred[0][3], Q1 = swred[0][4], Q2 = swred[0][5];
        #pragma unroll
        for (int w = 1; w < 8; w++) {
            P0 += swred[w][0]; P1 += swred[w][1]; P2 += swred[w][2];
            Q0 += swred[w][3]; Q1 += swred[w][4]; Q2 += swred[w][5];
        }
        Q0 += B3[c * 3 + 0]; Q1 += B3[c * 3 + 1]; Q2 += B3[c * 3 + 2];
        float* pq = &g_PQ[c][i][0][0];
        pq[0] = P0; pq[1] = P1; pq[2] = P2; pq[3] = Q0; pq[4] = Q1; pq[5] = Q2;
        for (int j = 0; j < m; j++) {
            unsigned p = spay[j];
            int   kk = (int)(p & 255u);
            float d  = (p & 256u) ? 1.0f : -1.0f;
            float a  = sA[kk], bb = sB[kk];
            float u0 = sW3[kk][0], u1 = sW3[kk][1], u2 = sW3[kk][2];
            P0 = fmaf(d * a,  u0, P0); P1 = fmaf(d * a,  u1, P1); P2 = fmaf(d * a,  u2, P2);
            Q0 = fmaf(d * bb, u0, Q0); Q1 = fmaf(d * bb, u1, Q1); Q2 = fmaf(d * bb, u2, Q2);
            g_xc[c][i][j] = skey[j];
            float* pq2 = &g_PQ[c][i][j + 1][0];
            pq2[0] = P0; pq2[1] = P1; pq2[2] = P2; pq2[3] = Q0; pq2[4] = Q1; pq2[5] = Q2;
        }
    }
}

// ---------------------------------------------------------------------------
// K3: evaluation. p = n*16 + c; out[p*3 + o]
// ---------------------------------------------------------------------------
__global__ void __launch_bounds__(256) k_eval(const float* __restrict__ X,
                                              float* __restrict__ out)
{
    __shared__ float st[CHN][HID];
    int tid = threadIdx.x;
    for (int q = tid; q < CHN * HID; q += 256)
        (&st[0][0])[q] = (&g_t[0][0])[q];
    __syncthreads();

    int p = blockIdx.x * 256 + tid;
    float x = X[p];
    int c = p & 15;

    // level 1: interval (8 steps, shared)
    int lo = 0, hi = HID;
    #pragma unroll
    for (int s = 0; s < 8; s++) {
        int mid = (lo + hi) >> 1;
        if (st[c][mid] <= x) lo = mid + 1; else hi = mid;
    }
    int i = lo;

    // level 2: segment within interval
    int m = g_cnt[c][i];
    int j = 0, jh = m;
    while (j < jh) {
        int mid = (j + jh) >> 1;
        if (g_xc[c][i][mid] <= x) j = mid + 1; else jh = mid;
    }

    const float4* pq = (const float4*)&g_PQ[c][i][j][0];
    float4 a = pq[0];
    float4 b = pq[1];
    float* o = out + p * 3;
    o[0] = fmaf(a.x, x, a.w);
    o[1] = fmaf(a.y, x, b.x);
    o[2] = fmaf(a.z, x, b.y);
}

// ---------------------------------------------------------------------------
extern "C" void kernel_launch(void* const* d_in, const int* in_sizes, int n_in,
                              void* d_out, int out_size)
{
    const float* x  = (const float*)d_in[0];
    const float* W1 = (const float*)d_in[1];
    const float* b1 = (const float*)d_in[2];
    const float* W2 = (const float*)d_in[3];
    const float* b2 = (const float*)d_in[4];
    const float* W3 = (const float*)d_in[5];
    const float* b3 = (const float*)d_in[6];
    float* out = (float*)d_out;

    k_sort  <<<CHN, 256>>>(W1, b1);
    k_gsum  <<<dim3(NG, CHN), 256>>>(W2);
    k_prefix<<<dim3(NG, CHN), 256>>>(W2);
    k_seg   <<<dim3(NIV, CHN), 256>>>(b2, W3, b3);
    k_eval  <<<(32768 * CHN) / 256, 256>>>(x, out);
}

// round 3
// speedup vs baseline: 1.7317x; 1.1190x over previous
#include <cuda_runtime.h>
#include <cuda_bf16.h>
#include <float.h>

// ============================================================================
// KolmogorovArnoldNetwork: exact piecewise-linear reformulation.
// R3: warp-per-interval k_seg (no block barriers in hot path, parallel
//     emission), sentinel-scan k_eval (no g_cnt dependent load).
// ============================================================================

#define CHN   16
#define HID   256
#define NIV   257
#define XMAXV 64.0f
#define NG    16
#define GS    16

// Scratch (device globals; no allocation)
__device__ float g_t   [CHN][HID];
__device__ int   g_idx [CHN][HID];
__device__ float g_ca0 [CHN][HID];
__device__ float g_cb0 [CHN][HID];
__device__ float g_ca1 [CHN][HID];
__device__ float g_cb1 [CHN][HID];
__device__ float g_SbA [CHN][NG][HID];
__device__ float g_SbB [CHN][NG][HID];
__device__ float g_StA [CHN][NG][HID];
__device__ float g_StB [CHN][NG][HID];
__device__ float g_A   [CHN][NIV][HID];
__device__ float g_Bv  [CHN][NIV][HID];
__device__ float g_xc  [CHN][NIV][NIV];       // sorted crossings + FLT_MAX sentinel
__device__ __align__(16) float g_PQ[CHN][NIV][NIV][8];

// ---------------------------------------------------------------------------
// K1-sort: per channel, sort thresholds, emit base/toggle coeffs by sorted pos
// ---------------------------------------------------------------------------
__global__ void __launch_bounds__(256) k_sort(const float* __restrict__ W1,
                                              const float* __restrict__ B1)
{
    int c   = blockIdx.x;
    int tid = threadIdx.x;

    __shared__ float    key[HID];
    __shared__ unsigned idx[HID];
    __shared__ float    sw1[HID], sb1[HID];

    float w1 = W1[c * HID + tid];
    float b1 = B1[c * HID + tid];
    sw1[tid] = w1; sb1[tid] = b1;

    float t = (w1 != 0.0f) ? (-b1 / w1) : 3.0e38f;
    key[tid] = t;
    idx[tid] = (unsigned)tid;

    for (unsigned size = 2; size <= HID; size <<= 1) {
        for (unsigned stride = size >> 1; stride; stride >>= 1) {
            __syncthreads();
            unsigned partner = (unsigned)tid ^ stride;
            if (partner > (unsigned)tid) {
                bool up = ((tid & size) == 0);
                float k1 = key[tid], k2 = key[partner];
                if ((k1 > k2) == up) {
                    key[tid] = k2; key[partner] = k1;
                    unsigned v = idx[tid]; idx[tid] = idx[partner]; idx[partner] = v;
                }
            }
        }
    }
    __syncthreads();

    g_t[c][tid] = key[tid];
    unsigned h = idx[tid];
    g_idx[c][tid] = (int)h;

    float w = sw1[h], b = sb1[h];
    bool base = (w < 0.0f) || (w == 0.0f && b > 0.0f);
    g_ca0[c][tid] = base ? w : 0.0f;
    g_cb0[c][tid] = base ? b : 0.0f;
    float s = (w > 0.0f) ? 1.0f : ((w < 0.0f) ? -1.0f : 0.0f);
    g_ca1[c][tid] = s * w;
    g_cb1[c][tid] = s * b;
}

// ---------------------------------------------------------------------------
// K1a: per (group, channel): base partial + toggle group total
// ---------------------------------------------------------------------------
__global__ void __launch_bounds__(256) k_gsum(const float* __restrict__ W2)
{
    int g = blockIdx.x, c = blockIdx.y, k = threadIdx.x;

    float sbA = 0.f, sbB = 0.f, stA = 0.f, stB = 0.f;
    #pragma unroll
    for (int jj = 0; jj < GS; jj++) {
        int j = g * GS + jj;
        int h = g_idx[c][j];
        float w2 = W2[(c * HID + h) * HID + k];
        sbA = fmaf(g_ca0[c][j], w2, sbA);
        sbB = fmaf(g_cb0[c][j], w2, sbB);
        stA = fmaf(g_ca1[c][j], w2, stA);
        stB = fmaf(g_cb1[c][j], w2, stB);
    }
    g_SbA[c][g][k] = sbA; g_SbB[c][g][k] = sbB;
    g_StA[c][g][k] = stA; g_StB[c][g][k] = stB;
}

// ---------------------------------------------------------------------------
// K1b: per (group, channel): offset from partials, 16-step local prefix
// ---------------------------------------------------------------------------
__global__ void __launch_bounds__(256) k_prefix(const float* __restrict__ W2)
{
    int g = blockIdx.x, c = blockIdx.y, k = threadIdx.x;

    float A = 0.f, B = 0.f;
    #pragma unroll
    for (int g2 = 0; g2 < NG; g2++) {
        A += g_SbA[c][g2][k];
        B += g_SbB[c][g2][k];
    }
    for (int g2 = 0; g2 < g; g2++) {
        A += g_StA[c][g2][k];
        B += g_StB[c][g2][k];
    }
    if (g == 0) { g_A[c][0][k] = A; g_Bv[c][0][k] = B; }

    #pragma unroll
    for (int jj = 0; jj < GS; jj++) {
        int j = g * GS + jj;
        int h = g_idx[c][j];
        float w2 = W2[(c * HID + h) * HID + k];
        A = fmaf(g_ca1[c][j], w2, A);
        B = fmaf(g_cb1[c][j], w2, B);
        g_A[c][j + 1][k] = A; g_Bv[c][j + 1][k] = B;
    }
}

// ---------------------------------------------------------------------------
// K2: warp-per-interval. 8 intervals per CTA; grid (33, 16).
// ---------------------------------------------------------------------------
#define SEG_CAP 32

__global__ void __launch_bounds__(256) k_seg(const float* __restrict__ B2,
                                             const float* __restrict__ W3,
                                             const float* __restrict__ B3)
{
    int c    = blockIdx.y;
    int tid  = threadIdx.x;
    int w    = tid >> 5;
    int lane = tid & 31;
    int i    = blockIdx.x * 8 + w;

    __shared__ float    sW3[HID][3];
    __shared__ float    sA [8][HID];
    __shared__ float    sB [8][HID];
    __shared__ float    sxc[8][SEG_CAP];
    __shared__ unsigned spay[8][SEG_CAP];

    for (int k = tid; k < HID; k += 256) {
        sW3[k][0] = W3[(c * HID + k) * 3 + 0];
        sW3[k][1] = W3[(c * HID + k) * 3 + 1];
        sW3[k][2] = W3[(c * HID + k) * 3 + 2];
    }
    __syncthreads();

    if (i > 256) return;

    float lo = (i == 0)   ? -XMAXV : g_t[c][i - 1];
    float hi = (i == 256) ?  XMAXV : g_t[c][i];
    lo = fminf(fmaxf(lo, -XMAXV), XMAXV);
    hi = fminf(fmaxf(hi, -XMAXV), XMAXV);
    if (hi < lo) hi = lo;

    float acc0 = 0.f, acc1 = 0.f, acc2 = 0.f, acc3 = 0.f, acc4 = 0.f, acc5 = 0.f;
    int m = 0;

    #pragma unroll
    for (int q = 0; q < 8; q++) {
        int k = q * 32 + lane;
        float a  = g_A [c][i][k];
        float bb = g_Bv[c][i][k] + B2[c * HID + k];
        sA[w][k] = a; sB[w][k] = bb;

        float gl = fmaf(a, lo, bb);
        float gh = fmaf(a, hi, bb);
        if (gl > 0.0f) {
            float u0 = sW3[k][0], u1 = sW3[k][1], u2 = sW3[k][2];
            acc0 = fmaf(a,  u0, acc0); acc1 = fmaf(a,  u1, acc1); acc2 = fmaf(a,  u2, acc2);
            acc3 = fmaf(bb, u0, acc3); acc4 = fmaf(bb, u1, acc4); acc5 = fmaf(bb, u2, acc5);
        }
        bool has = ((gl > 0.0f) != (gh > 0.0f));
        unsigned mask = __ballot_sync(0xFFFFFFFFu, has);
        if (has) {
            int slot = m + __popc(mask & ((1u << lane) - 1u));
            if (slot < SEG_CAP) {
                sxc [w][slot] = lo + (hi - lo) * (gl / (gl - gh));
                spay[w][slot] = (unsigned)k | ((gh > 0.0f) ? 256u : 0u);
            }
        }
        m += __popc(mask);
    }

    // warp-reduce 6 accumulators, broadcast to all lanes
    #pragma unroll
    for (int off = 16; off; off >>= 1) {
        acc0 += __shfl_down_sync(0xFFFFFFFFu, acc0, off);
        acc1 += __shfl_down_sync(0xFFFFFFFFu, acc1, off);
        acc2 += __shfl_down_sync(0xFFFFFFFFu, acc2, off);
        acc3 += __shfl_down_sync(0xFFFFFFFFu, acc3, off);
        acc4 += __shfl_down_sync(0xFFFFFFFFu, acc4, off);
        acc5 += __shfl_down_sync(0xFFFFFFFFu, acc5, off);
    }
    float P0 = __shfl_sync(0xFFFFFFFFu, acc0, 0);
    float P1 = __shfl_sync(0xFFFFFFFFu, acc1, 0);
    float P2 = __shfl_sync(0xFFFFFFFFu, acc2, 0);
    float Q0 = __shfl_sync(0xFFFFFFFFu, acc3, 0) + B3[c * 3 + 0];
    float Q1 = __shfl_sync(0xFFFFFFFFu, acc4, 0) + B3[c * 3 + 1];
    float Q2 = __shfl_sync(0xFFFFFFFFu, acc5, 0) + B3[c * 3 + 2];

    __syncwarp();

    if (lane == 0) {
        float* pq = &g_PQ[c][i][0][0];
        pq[0] = P0; pq[1] = P1; pq[2] = P2; pq[3] = Q0; pq[4] = Q1; pq[5] = Q2;
        g_xc[c][i][m] = FLT_MAX;   // sentinel
    }

    if (m == 0) return;

    if (m <= SEG_CAP) {
        // parallel emission: each lane with a crossing computes its rank and
        // the prefix of deltas up to (and including) itself.
        bool  own = (lane < m);
        float xcL = own ? sxc[w][lane] : FLT_MAX;
        int   r   = 0;
        float S0 = P0, S1 = P1, S2 = P2, S3 = Q0, S4 = Q1, S5 = Q2;
        for (int l2 = 0; l2 < m; l2++) {
            float o = sxc[w][l2];
            bool before = (o < xcL) || (o == xcL && l2 < lane);
            if (own && before) r++;
            bool incl = own && (before || l2 == lane);
            if (incl) {
                unsigned p = spay[w][l2];
                int   kk = (int)(p & 255u);
                float d  = (p & 256u) ? 1.0f : -1.0f;
                float a  = d * sA[w][kk];
                float bb = d * sB[w][kk];
                float u0 = sW3[kk][0], u1 = sW3[kk][1], u2 = sW3[kk][2];
                S0 = fmaf(a,  u0, S0); S1 = fmaf(a,  u1, S1); S2 = fmaf(a,  u2, S2);
                S3 = fmaf(bb, u0, S3); S4 = fmaf(bb, u1, S4); S5 = fmaf(bb, u2, S5);
            }
        }
        if (own) {
            g_xc[c][i][r] = xcL;
            float* pq = &g_PQ[c][i][r + 1][0];
            pq[0] = S0; pq[1] = S1; pq[2] = S2; pq[3] = S3; pq[4] = S4; pq[5] = S5;
        }
    } else if (lane == 0) {
        // pathological overflow fallback: serial, fully correct
        float S0 = P0, S1 = P1, S2 = P2, S3 = Q0, S4 = Q1, S5 = Q2;
        float last = -FLT_MAX; int lastk = -1;
        for (int j = 0; j < m; j++) {
            float best = FLT_MAX; int bk = -1; float bd = 0.f;
            for (int k = 0; k < HID; k++) {
                float a  = sA[w][k], bb = sB[w][k];
                float gl = fmaf(a, lo, bb), gh = fmaf(a, hi, bb);
                if ((gl > 0.0f) != (gh > 0.0f)) {
                    float xc = lo + (hi - lo) * (gl / (gl - gh));
                    bool gt = (xc > last) || (xc == last && k > lastk);
                    if (gt && (xc < best || (xc == best && k < bk))) {
                        best = xc; bk = k; bd = (gh > 0.0f) ? 1.0f : -1.0f;
                    }
                }
            }
            last = best; lastk = bk;
            float a  = bd * sA[w][bk];
            float bb = bd * sB[w][bk];
            float u0 = sW3[bk][0], u1 = sW3[bk][1], u2 = sW3[bk][2];
            S0 = fmaf(a,  u0, S0); S1 = fmaf(a,  u1, S1); S2 = fmaf(a,  u2, S2);
            S3 = fmaf(bb, u0, S3); S4 = fmaf(bb, u1, S4); S5 = fmaf(bb, u2, S5);
            g_xc[c][i][j] = best;
            float* pq = &g_PQ[c][i][j + 1][0];
            pq[0] = S0; pq[1] = S1; pq[2] = S2; pq[3] = S3; pq[4] = S4; pq[5] = S5;
        }
    }
}

// ---------------------------------------------------------------------------
// K3: evaluation. p = n*16 + c; out[p*3 + o]
// ---------------------------------------------------------------------------
__global__ void __launch_bounds__(256) k_eval(const float* __restrict__ X,
                                              float* __restrict__ out)
{
    __shared__ float st[CHN][HID];
    int tid = threadIdx.x;
    for (int q = tid; q < CHN * HID; q += 256)
        (&st[0][0])[q] = (&g_t[0][0])[q];
    __syncthreads();

    int p = blockIdx.x * 256 + tid;
    float x = X[p];
    int c = p & 15;

    // level 1: interval (8 steps, shared)
    int lo = 0, hi = HID;
    #pragma unroll
    for (int s = 0; s < 8; s++) {
        int mid = (lo + hi) >> 1;
        if (st[c][mid] <= x) lo = mid + 1; else hi = mid;
    }
    int i = lo;

    // level 2: sentinel-terminated linear scan (avg ~1 load)
    const float* xr = &g_xc[c][i][0];
    int j = 0;
    while (xr[j] <= x) j++;

    const float4* pq = (const float4*)&g_PQ[c][i][j][0];
    float4 a = pq[0];
    float4 b = pq[1];
    float* o = out + p * 3;
    o[0] = fmaf(a.x, x, a.w);
    o[1] = fmaf(a.y, x, b.x);
    o[2] = fmaf(a.z, x, b.y);
}

// ---------------------------------------------------------------------------
extern "C" void kernel_launch(void* const* d_in, const int* in_sizes, int n_in,
                              void* d_out, int out_size)
{
    const float* x  = (const float*)d_in[0];
    const float* W1 = (const float*)d_in[1];
    const float* b1 = (const float*)d_in[2];
    const float* W2 = (const float*)d_in[3];
    const float* b2 = (const float*)d_in[4];
    const float* W3 = (const float*)d_in[5];
    const float* b3 = (const float*)d_in[6];
    float* out = (float*)d_out;

    k_sort  <<<CHN, 256>>>(W1, b1);
    k_gsum  <<<dim3(NG, CHN), 256>>>(W2);
    k_prefix<<<dim3(NG, CHN), 256>>>(W2);
    k_seg   <<<dim3(33, CHN), 256>>>(b2, W3, b3);
    k_eval  <<<(32768 * CHN) / 256, 256>>>(x, out);
}

// round 4
// speedup vs baseline: 1.9131x; 1.1048x over previous
#include <cuda_runtime.h>
#include <cuda_bf16.h>
#include <float.h>

// ============================================================================
// KolmogorovArnoldNetwork: exact piecewise-linear reformulation.
// R4: fuse prefix+segment into k_pseg (prefix rows live in SMEM, no g_A/g_Bv
//     global round-trip); coalesced k_eval output via SMEM staging.
// Pipeline: k_sort (16 CTAs) -> k_gsum (256) -> k_pseg (256) -> k_eval (2048)
// ============================================================================

#define CHN   16
#define HID   256
#define NIV   257
#define XMAXV 64.0f
#define NG    16
#define GS    16

// Scratch (device globals; no allocation)
__device__ float g_t   [CHN][HID];
__device__ int   g_idx [CHN][HID];
__device__ float g_ca0 [CHN][HID];
__device__ float g_cb0 [CHN][HID];
__device__ float g_ca1 [CHN][HID];
__device__ float g_cb1 [CHN][HID];
__device__ float g_SbA [CHN][NG][HID];
__device__ float g_SbB [CHN][NG][HID];
__device__ float g_StA [CHN][NG][HID];
__device__ float g_StB [CHN][NG][HID];
__device__ float g_xc  [CHN][NIV][NIV];       // sorted crossings + FLT_MAX sentinel
__device__ __align__(16) float g_PQ[CHN][NIV][NIV][8];

// ---------------------------------------------------------------------------
// K1-sort: per channel, sort thresholds, emit base/toggle coeffs by sorted pos
// ---------------------------------------------------------------------------
__global__ void __launch_bounds__(256) k_sort(const float* __restrict__ W1,
                                              const float* __restrict__ B1)
{
    int c   = blockIdx.x;
    int tid = threadIdx.x;

    __shared__ float    key[HID];
    __shared__ unsigned idx[HID];
    __shared__ float    sw1[HID], sb1[HID];

    float w1 = W1[c * HID + tid];
    float b1 = B1[c * HID + tid];
    sw1[tid] = w1; sb1[tid] = b1;

    float t = (w1 != 0.0f) ? (-b1 / w1) : 3.0e38f;
    key[tid] = t;
    idx[tid] = (unsigned)tid;

    for (unsigned size = 2; size <= HID; size <<= 1) {
        for (unsigned stride = size >> 1; stride; stride >>= 1) {
            __syncthreads();
            unsigned partner = (unsigned)tid ^ stride;
            if (partner > (unsigned)tid) {
                bool up = ((tid & size) == 0);
                float k1 = key[tid], k2 = key[partner];
                if ((k1 > k2) == up) {
                    key[tid] = k2; key[partner] = k1;
                    unsigned v = idx[tid]; idx[tid] = idx[partner]; idx[partner] = v;
                }
            }
        }
    }
    __syncthreads();

    g_t[c][tid] = key[tid];
    unsigned h = idx[tid];
    g_idx[c][tid] = (int)h;

    float w = sw1[h], b = sb1[h];
    bool base = (w < 0.0f) || (w == 0.0f && b > 0.0f);
    g_ca0[c][tid] = base ? w : 0.0f;
    g_cb0[c][tid] = base ? b : 0.0f;
    float s = (w > 0.0f) ? 1.0f : ((w < 0.0f) ? -1.0f : 0.0f);
    g_ca1[c][tid] = s * w;
    g_cb1[c][tid] = s * b;
}

// ---------------------------------------------------------------------------
// K1a: per (group, channel): base partial + toggle group total
// ---------------------------------------------------------------------------
__global__ void __launch_bounds__(256) k_gsum(const float* __restrict__ W2)
{
    int g = blockIdx.x, c = blockIdx.y, k = threadIdx.x;

    float sbA = 0.f, sbB = 0.f, stA = 0.f, stB = 0.f;
    #pragma unroll
    for (int jj = 0; jj < GS; jj++) {
        int j = g * GS + jj;
        int h = g_idx[c][j];
        float w2 = W2[(c * HID + h) * HID + k];
        sbA = fmaf(g_ca0[c][j], w2, sbA);
        sbB = fmaf(g_cb0[c][j], w2, sbB);
        stA = fmaf(g_ca1[c][j], w2, stA);
        stB = fmaf(g_cb1[c][j], w2, stB);
    }
    g_SbA[c][g][k] = sbA; g_SbB[c][g][k] = sbB;
    g_StA[c][g][k] = stA; g_StB[c][g][k] = stB;
}

// ---------------------------------------------------------------------------
// K2 fused: per (group, channel) CTA.
//   Phase 1: 17 prefix rows (A,B) -> SMEM (b2 folded into base).
//   Phase 2: 8 warps x ~2 intervals, warp-per-interval segment extraction.
// ---------------------------------------------------------------------------
#define SEG_CAP 32

__global__ void __launch_bounds__(256) k_pseg(const float* __restrict__ W2,
                                              const float* __restrict__ B2,
                                              const float* __restrict__ W3,
                                              const float* __restrict__ B3)
{
    int g    = blockIdx.x;   // 0..15
    int c    = blockIdx.y;
    int tid  = threadIdx.x;
    int w    = tid >> 5;
    int lane = tid & 31;

    __shared__ float    sA [17][HID];
    __shared__ float    sB [17][HID];
    __shared__ float    sW3[HID][3];
    __shared__ float    sxc[8][SEG_CAP];
    __shared__ unsigned spay[8][SEG_CAP];

    // ---- Phase 1: prefix rows into SMEM (thread = k) ----
    {
        int k = tid;
        sW3[k][0] = W3[(c * HID + k) * 3 + 0];
        sW3[k][1] = W3[(c * HID + k) * 3 + 1];
        sW3[k][2] = W3[(c * HID + k) * 3 + 2];

        float A = 0.f;
        float B = B2[c * HID + k];               // fold b2 into base
        #pragma unroll
        for (int g2 = 0; g2 < NG; g2++) {        // full base
            A += g_SbA[c][g2][k];
            B += g_SbB[c][g2][k];
        }
        for (int g2 = 0; g2 < g; g2++) {         // earlier groups' toggles
            A += g_StA[c][g2][k];
            B += g_StB[c][g2][k];
        }
        sA[0][k] = A; sB[0][k] = B;

        #pragma unroll
        for (int jj = 0; jj < GS; jj++) {
            int j = g * GS + jj;
            int h = g_idx[c][j];
            float w2 = W2[(c * HID + h) * HID + k];
            A = fmaf(g_ca1[c][j], w2, A);
            B = fmaf(g_cb1[c][j], w2, B);
            sA[jj + 1][k] = A; sB[jj + 1][k] = B;
        }
    }
    __syncthreads();

    // ---- Phase 2: warp-per-interval ----
    float bQ0 = B3[c * 3 + 0], bQ1 = B3[c * 3 + 1], bQ2 = B3[c * 3 + 2];
    int nR = (g == NG - 1) ? 17 : 16;            // CTA 15 also owns interval 256

    for (int r = w; r < nR; r += 8) {
        int i = g * GS + r;                      // global interval index

        float lo = (i == 0)   ? -XMAXV : g_t[c][i - 1];
        float hi = (i == 256) ?  XMAXV : g_t[c][i];
        lo = fminf(fmaxf(lo, -XMAXV), XMAXV);
        hi = fminf(fmaxf(hi, -XMAXV), XMAXV);
        if (hi < lo) hi = lo;

        float acc0 = 0.f, acc1 = 0.f, acc2 = 0.f, acc3 = 0.f, acc4 = 0.f, acc5 = 0.f;
        int m = 0;

        #pragma unroll
        for (int q = 0; q < 8; q++) {
            int k = q * 32 + lane;
            float a  = sA[r][k];
            float bb = sB[r][k];

            float gl = fmaf(a, lo, bb);
            float gh = fmaf(a, hi, bb);
            if (gl > 0.0f) {
                float u0 = sW3[k][0], u1 = sW3[k][1], u2 = sW3[k][2];
                acc0 = fmaf(a,  u0, acc0); acc1 = fmaf(a,  u1, acc1); acc2 = fmaf(a,  u2, acc2);
                acc3 = fmaf(bb, u0, acc3); acc4 = fmaf(bb, u1, acc4); acc5 = fmaf(bb, u2, acc5);
            }
            bool has = ((gl > 0.0f) != (gh > 0.0f));
            unsigned mask = __ballot_sync(0xFFFFFFFFu, has);
            if (has) {
                int slot = m + __popc(mask & ((1u << lane) - 1u));
                if (slot < SEG_CAP) {
                    sxc [w][slot] = lo + (hi - lo) * (gl / (gl - gh));
                    spay[w][slot] = (unsigned)k | ((gh > 0.0f) ? 256u : 0u);
                }
            }
            m += __popc(mask);
        }

        #pragma unroll
        for (int off = 16; off; off >>= 1) {
            acc0 += __shfl_down_sync(0xFFFFFFFFu, acc0, off);
            acc1 += __shfl_down_sync(0xFFFFFFFFu, acc1, off);
            acc2 += __shfl_down_sync(0xFFFFFFFFu, acc2, off);
            acc3 += __shfl_down_sync(0xFFFFFFFFu, acc3, off);
            acc4 += __shfl_down_sync(0xFFFFFFFFu, acc4, off);
            acc5 += __shfl_down_sync(0xFFFFFFFFu, acc5, off);
        }
        float P0 = __shfl_sync(0xFFFFFFFFu, acc0, 0);
        float P1 = __shfl_sync(0xFFFFFFFFu, acc1, 0);
        float P2 = __shfl_sync(0xFFFFFFFFu, acc2, 0);
        float Q0 = __shfl_sync(0xFFFFFFFFu, acc3, 0) + bQ0;
        float Q1 = __shfl_sync(0xFFFFFFFFu, acc4, 0) + bQ1;
        float Q2 = __shfl_sync(0xFFFFFFFFu, acc5, 0) + bQ2;

        __syncwarp();

        if (lane == 0) {
            float* pq = &g_PQ[c][i][0][0];
            pq[0] = P0; pq[1] = P1; pq[2] = P2; pq[3] = Q0; pq[4] = Q1; pq[5] = Q2;
            g_xc[c][i][m] = FLT_MAX;   // sentinel
        }

        if (m == 0) continue;

        if (m <= SEG_CAP) {
            // parallel emission: rank + inclusive prefix per owning lane
            bool  own = (lane < m);
            float xcL = own ? sxc[w][lane] : FLT_MAX;
            int   rk  = 0;
            float S0 = P0, S1 = P1, S2 = P2, S3 = Q0, S4 = Q1, S5 = Q2;
            for (int l2 = 0; l2 < m; l2++) {
                float o = sxc[w][l2];
                bool before = (o < xcL) || (o == xcL && l2 < lane);
                if (own && before) rk++;
                bool incl = own && (before || l2 == lane);
                if (incl) {
                    unsigned p = spay[w][l2];
                    int   kk = (int)(p & 255u);
                    float d  = (p & 256u) ? 1.0f : -1.0f;
                    float a  = d * sA[r][kk];
                    float bb = d * sB[r][kk];
                    float u0 = sW3[kk][0], u1 = sW3[kk][1], u2 = sW3[kk][2];
                    S0 = fmaf(a,  u0, S0); S1 = fmaf(a,  u1, S1); S2 = fmaf(a,  u2, S2);
                    S3 = fmaf(bb, u0, S3); S4 = fmaf(bb, u1, S4); S5 = fmaf(bb, u2, S5);
                }
            }
            if (own) {
                g_xc[c][i][rk] = xcL;
                float* pq = &g_PQ[c][i][rk + 1][0];
                pq[0] = S0; pq[1] = S1; pq[2] = S2; pq[3] = S3; pq[4] = S4; pq[5] = S5;
            }
        } else if (lane == 0) {
            // pathological overflow fallback: serial, fully correct
            float S0 = P0, S1 = P1, S2 = P2, S3 = Q0, S4 = Q1, S5 = Q2;
            float last = -FLT_MAX; int lastk = -1;
            for (int j = 0; j < m; j++) {
                float best = FLT_MAX; int bk = -1; float bd = 0.f;
                for (int k = 0; k < HID; k++) {
                    float a  = sA[r][k], bb = sB[r][k];
                    float gl = fmaf(a, lo, bb), gh = fmaf(a, hi, bb);
                    if ((gl > 0.0f) != (gh > 0.0f)) {
                        float xc = lo + (hi - lo) * (gl / (gl - gh));
                        bool gt = (xc > last) || (xc == last && k > lastk);
                        if (gt && (xc < best || (xc == best && k < bk))) {
                            best = xc; bk = k; bd = (gh > 0.0f) ? 1.0f : -1.0f;
                        }
                    }
                }
                last = best; lastk = bk;
                float a  = bd * sA[r][bk];
                float bb = bd * sB[r][bk];
                float u0 = sW3[bk][0], u1 = sW3[bk][1], u2 = sW3[bk][2];
                S0 = fmaf(a,  u0, S0); S1 = fmaf(a,  u1, S1); S2 = fmaf(a,  u2, S2);
                S3 = fmaf(bb, u0, S3); S4 = fmaf(bb, u1, S4); S5 = fmaf(bb, u2, S5);
                g_xc[c][i][j] = best;
                float* pq = &g_PQ[c][i][j + 1][0];
                pq[0] = S0; pq[1] = S1; pq[2] = S2; pq[3] = S3; pq[4] = S4; pq[5] = S5;
            }
        }
    }
}

// ---------------------------------------------------------------------------
// K3: evaluation. p = n*16 + c; out[p*3 + o], coalesced via SMEM staging.
// ---------------------------------------------------------------------------
__global__ void __launch_bounds__(256) k_eval(const float* __restrict__ X,
                                              float* __restrict__ out)
{
    __shared__ float st[CHN][HID];
    __shared__ float so[768];
    int tid = threadIdx.x;
    for (int q = tid; q < CHN * HID; q += 256)
        (&st[0][0])[q] = (&g_t[0][0])[q];
    __syncthreads();

    int p = blockIdx.x * 256 + tid;
    float x = X[p];
    int c = p & 15;

    // level 1: interval (8 steps, shared)
    int lo = 0, hi = HID;
    #pragma unroll
    for (int s = 0; s < 8; s++) {
        int mid = (lo + hi) >> 1;
        if (st[c][mid] <= x) lo = mid + 1; else hi = mid;
    }
    int i = lo;

    // level 2: sentinel-terminated linear scan (avg ~1 load)
    const float* xr = &g_xc[c][i][0];
    int j = 0;
    while (xr[j] <= x) j++;

    const float4* pq = (const float4*)&g_PQ[c][i][j][0];
    float4 a = pq[0];
    float4 b = pq[1];
    so[tid * 3 + 0] = fmaf(a.x, x, a.w);
    so[tid * 3 + 1] = fmaf(a.y, x, b.x);
    so[tid * 3 + 2] = fmaf(a.z, x, b.y);
    __syncthreads();

    float* ob = out + blockIdx.x * 768;
    ob[tid]       = so[tid];
    ob[tid + 256] = so[tid + 256];
    ob[tid + 512] = so[tid + 512];
}

// ---------------------------------------------------------------------------
extern "C" void kernel_launch(void* const* d_in, const int* in_sizes, int n_in,
                              void* d_out, int out_size)
{
    const float* x  = (const float*)d_in[0];
    const float* W1 = (const float*)d_in[1];
    const float* b1 = (const float*)d_in[2];
    const float* W2 = (const float*)d_in[3];
    const float* b2 = (const float*)d_in[4];
    const float* W3 = (const float*)d_in[5];
    const float* b3 = (const float*)d_in[6];
    float* out = (float*)d_out;

    k_sort<<<CHN, 256>>>(W1, b1);
    k_gsum<<<dim3(NG, CHN), 256>>>(W2);
    k_pseg<<<dim3(NG, CHN), 256>>>(W2, b2, W3, b3);
    k_eval<<<(32768 * CHN) / 256, 256>>>(x, out);
}